// round 15
// baseline (speedup 1.0000x reference)
#include <cuda_runtime.h>
#include <cstdint>

#define BATCH 64
#define TT    2048
#define HID   128
#define G3    384
#define NPROD 84
#define NTHR  384
#define NCH   ((TT + NPROD - 1) / NPROD)   // 25 chunks

__device__ __align__(16) float g_gi[(size_t)TT * BATCH * G3];
__device__ int g_cnt[NCH];

__device__ __forceinline__ unsigned long long pack2(float lo, float hi) {
    unsigned long long r;
    asm("mov.b64 %0, {%1, %2};" : "=l"(r) : "f"(lo), "f"(hi));
    return r;
}
__device__ __forceinline__ void unpack2(unsigned long long v, float &lo, float &hi) {
    asm("mov.b64 {%0, %1}, %2;" : "=f"(lo), "=f"(hi) : "l"(v));
}
__device__ __forceinline__ void ffma2(unsigned long long &d, unsigned long long a,
                                      unsigned long long b) {
    asm("fma.rn.f32x2 %0, %1, %2, %0;" : "+l"(d) : "l"(a), "l"(b));
}
__device__ __forceinline__ unsigned long long mul2(unsigned long long a, unsigned long long b) {
    unsigned long long r;
    asm("mul.rn.f32x2 %0, %1, %2;" : "=l"(r) : "l"(a), "l"(b));
    return r;
}
__device__ __forceinline__ float tanh_apx(float x) {
    float y;
    asm("tanh.approx.f32 %0, %1;" : "=f"(y) : "f"(x));
    return y;
}
__device__ __forceinline__ void cp_async16(uint32_t dst_smem, const void* src) {
    asm volatile("cp.async.cg.shared.global [%0], [%1], 16;"
                 :: "r"(dst_smem), "l"(src) : "memory");
}
__device__ __forceinline__ void wait_chunk(int c, int target) {
    volatile int* p = (volatile int*)&g_cnt[c];
    while (*p < target) __nanosleep(64);
    __threadfence();
}

__global__ void reset_kernel() {
    int i = threadIdx.x;
    if (i < NCH) g_cnt[i] = 0;
}

__global__ void __launch_bounds__(NTHR, 1)
gru_kernel(const float* __restrict__ x,      // [B, T, 128]
           const float* __restrict__ w_ih,   // [384, 128]
           const float* __restrict__ w_hh,   // [384, 128]
           const float* __restrict__ b_ih,   // [384]
           const float* __restrict__ b_hh,   // [384]
           const float* __restrict__ w_proj, // [64, 128]
           const float* __restrict__ b_proj, // [64]
           float* __restrict__ out)          // [64, 64]
{
    __shared__ float s_x[BATCH * HID];                  // producer staging (32 KB)
    __shared__ float s_h[HID];
    __shared__ float s_gh[G3];
    __shared__ alignas(16) float s_gi[3][G3];           // gi triple buffer (2-step cover)
    __shared__ float s_pool[HID];

    const int tid = threadIdx.x;

    if (blockIdx.x >= BATCH) {
        // ============================ PRODUCER (R5-proven, unchanged) ============================
        const int w = blockIdx.x - BATCH;
        unsigned long long wr[64];
        const unsigned long long* W =
            reinterpret_cast<const unsigned long long*>(w_ih) + (size_t)tid * 64;
        #pragma unroll
        for (int i = 0; i < 64; i++) wr[i] = W[i];
        const unsigned long long bias = pack2(b_ih[tid], 0.0f);

        for (int c = 0; c < NCH; c++) {
            const int t = c * NPROD + w;
            if (t >= TT) break;
            for (int idx = tid; idx < BATCH * HID; idx += NTHR)
                s_x[idx] = __ldcg(&x[(((size_t)(idx >> 7)) * TT + t) * HID + (idx & 127)]);
            __syncthreads();

            float* gout = g_gi + (size_t)t * BATCH * G3;
            for (int b = 0; b < BATCH; b++) {
                const ulonglong2* hx = reinterpret_cast<const ulonglong2*>(s_x + b * HID);
                unsigned long long a0 = bias, a1 = pack2(0.0f, 0.0f);
                #pragma unroll
                for (int i = 0; i < 32; i++) {
                    ulonglong2 v = hx[i];
                    ffma2(a0, wr[2 * i],     v.x);
                    ffma2(a1, wr[2 * i + 1], v.y);
                }
                float s0, s1, s2, s3;
                unpack2(a0, s0, s1);
                unpack2(a1, s2, s3);
                gout[b * G3 + tid] = (s0 + s1) + (s2 + s3);
            }
            __threadfence();
            __syncthreads();
            if (tid == 0) atomicAdd(&g_cnt[c], 1);
            __syncthreads();
        }
    } else {
        // ============================ CONSUMER ============================
        const int b = blockIdx.x;
        const bool rz = (tid < 2 * HID);     // r/z rows: gi additive, pre-scale 0.5
        unsigned long long wr[64];
        const unsigned long long* W =
            reinterpret_cast<const unsigned long long*>(w_hh) + (size_t)tid * 64;
        #pragma unroll
        for (int i = 0; i < 64; i++) wr[i] = W[i];
        if (rz) {
            const unsigned long long half2 = pack2(0.5f, 0.5f);
            #pragma unroll
            for (int i = 0; i < 64; i++) wr[i] = mul2(wr[i], half2);  // exact: x0.5
        }
        const float bias_s = rz ? 0.5f * b_hh[tid] : b_hh[tid];

        if (tid < HID) s_h[tid] = 0.0f;
        float pool = 0.0f;
        float h_j  = 0.0f;

        const float* gi_b = g_gi + (size_t)b * G3;

        wait_chunk(0, NPROD);
        if (tid < G3) s_gi[0][tid] = __ldcg(gi_b + tid);
        if (tid < G3 / 4)
            cp_async16((uint32_t)__cvta_generic_to_shared(&s_gi[1][tid * 4]),
                       gi_b + (size_t)1 * BATCH * G3 + tid * 4);
        asm volatile("cp.async.commit_group;" ::: "memory");
        __syncthreads();

        int cnext = 1;
        for (int t = 0; t < TT; t++) {
            // ---- schedule gi copy for t+2 (one group committed per step) ----
            if (t + 2 < TT) {
                if (t + 2 == cnext * NPROD) {
                    const int target = (TT - cnext * NPROD < NPROD) ? (TT - cnext * NPROD) : NPROD;
                    wait_chunk(cnext, target);
                    cnext++;
                }
                if (tid < G3 / 4) {
                    const float* src = gi_b + (size_t)(t + 2) * BATCH * G3 + tid * 4;
                    cp_async16((uint32_t)__cvta_generic_to_shared(&s_gi[(t + 2) % 3][tid * 4]), src);
                }
            }
            asm volatile("cp.async.commit_group;" ::: "memory");

            // ---- phase 1: gh = w_hh' . h + bias' (+ gi folded for r/z rows) ----
            float base = bias_s;
            if (rz) base = fmaf(0.5f, s_gi[t % 3][tid], bias_s);  // 0.5*(b_hh+gi)
            const ulonglong2* hp = reinterpret_cast<const ulonglong2*>(s_h);
            unsigned long long a0 = pack2(base, 0.0f), a1 = pack2(0.0f, 0.0f);
            unsigned long long a2 = pack2(0.0f, 0.0f), a3 = pack2(0.0f, 0.0f);
            #pragma unroll
            for (int i = 0; i < 16; i++) {
                ulonglong2 v0 = hp[2 * i];
                ulonglong2 v1 = hp[2 * i + 1];
                ffma2(a0, wr[4 * i],     v0.x);
                ffma2(a1, wr[4 * i + 1], v0.y);
                ffma2(a2, wr[4 * i + 2], v1.x);
                ffma2(a3, wr[4 * i + 3], v1.y);
            }
            float s0, s1, s2, s3, s4, s5, s6, s7;
            unpack2(a0, s0, s1);
            unpack2(a1, s2, s3);
            unpack2(a2, s4, s5);
            unpack2(a3, s6, s7);
            s_gh[tid] = ((s0 + s1) + (s2 + s3)) + ((s4 + s5) + (s6 + s7));

            asm volatile("cp.async.wait_group 2;" ::: "memory");
            __syncthreads();

            // ---- phase 2: gates (threads 0..127) — shortened chain ----
            if (tid < HID) {
                float x_r  = s_gh[tid];              // = 0.5*(gi_r + w_r.h + b_r)
                float x_z  = s_gh[HID + tid];        // = 0.5*(gi_z + w_z.h + b_z)
                float gh_n = s_gh[2 * HID + tid];    // = w_n.h + b_n (no gi)
                float gi_n = s_gi[t % 3][2 * HID + tid];
                float p = 0.5f * gh_n;
                float q = gi_n + p;
                float t_r = tanh_apx(x_r);
                float t_z = tanh_apx(x_z);           // parallel MUFU
                float cc  = fmaf(t_r, p, q);         // gi_n + sigmoid(.)*gh_n
                float n   = tanh_apx(cc);
                float z   = fmaf(0.5f, t_z, 0.5f);
                h_j = fmaf(z, h_j - n, n);
                pool += h_j;
                s_h[tid] = h_j;
            }
            __syncthreads();
        }

        // ---- mean pool + projection ----
        if (tid < HID) s_pool[tid] = pool * (1.0f / (float)TT);
        __syncthreads();
        if (tid < 64) {
            float acc = b_proj[tid];
            const float* wp = w_proj + tid * HID;
            #pragma unroll 8
            for (int j = 0; j < HID; j++) acc += wp[j] * s_pool[j];
            out[b * 64 + tid] = acc;
        }
    }
}

extern "C" void kernel_launch(void* const* d_in, const int* in_sizes, int n_in,
                              void* d_out, int out_size) {
    const float* x      = (const float*)d_in[0];
    const float* w_ih   = (const float*)d_in[1];
    const float* w_hh   = (const float*)d_in[2];
    const float* b_ih   = (const float*)d_in[3];
    const float* b_hh   = (const float*)d_in[4];
    const float* w_proj = (const float*)d_in[5];
    const float* b_proj = (const float*)d_in[6];
    float* out = (float*)d_out;

    reset_kernel<<<1, 32>>>();
    gru_kernel<<<BATCH + NPROD, NTHR>>>(x, w_ih, w_hh, b_ih, b_hh, w_proj, b_proj, out);
}